// round 2
// baseline (speedup 1.0000x reference)
#include <cuda_runtime.h>
#include <math.h>

// Problem dims
#define NB 1024
#define NH 2048
#define NV 8192
#define NL 8

// Ping-pong state buffers (device globals: no allocation in kernel_launch)
__device__ float g_buf0[NB * NH];
__device__ float g_buf1[NB * NH];

// GEMM tiling
constexpr int BM = 128;
constexpr int BN = 128;
constexpr int BK = 16;
constexpr int TM = 8;
constexpr int TN = 8;
constexpr int THREADS = (BM / TM) * (BN / TN);  // 256

// Fused layer: s_out = tanh(s_in + (s_in @ hh) * ih[token])
__global__ __launch_bounds__(THREADS)
void rnn_layer_kernel(const float* __restrict__ s_in,
                      const float* __restrict__ hh,     // [NH, NH] this layer
                      const float* __restrict__ ih,     // [NV, NH] this layer
                      const int* __restrict__ token,    // [NB] int32 (JAX x64-off)
                      float* __restrict__ s_out)
{
    // +4 pad on A rows to break bank conflicts on transposed stores
    __shared__ __align__(16) float As[BK][BM + 4];
    __shared__ __align__(16) float Bs[BK][BN];

    const int tid = threadIdx.x;
    const int rowBase = blockIdx.y * BM;   // batch tile
    const int colBase = blockIdx.x * BN;   // output-H tile

    const int tx = tid % (BN / TN);  // 0..15
    const int ty = tid / (BN / TN);  // 0..15

    float acc[TM][TN];
#pragma unroll
    for (int i = 0; i < TM; i++)
#pragma unroll
        for (int j = 0; j < TN; j++) acc[i][j] = 0.0f;

    for (int kt = 0; kt < NH; kt += BK) {
        // Load A tile (s_in[rowBase:+128, kt:+16]) transposed into As[k][m]
        // 512 float4 per tile, 2 per thread
#pragma unroll
        for (int p = 0; p < 2; p++) {
            int f = tid + p * 256;
            int ar = f >> 2;              // 0..127
            int ac4 = (f & 3) * 4;        // 0,4,8,12
            float4 v = *reinterpret_cast<const float4*>(
                &s_in[(size_t)(rowBase + ar) * NH + kt + ac4]);
            As[ac4 + 0][ar] = v.x;
            As[ac4 + 1][ar] = v.y;
            As[ac4 + 2][ar] = v.z;
            As[ac4 + 3][ar] = v.w;
        }
        // Load B tile (hh[kt:+16, colBase:+128])
#pragma unroll
        for (int p = 0; p < 2; p++) {
            int f = tid + p * 256;
            int br = f >> 5;              // 0..15
            int bc4 = (f & 31) * 4;       // 0..124
            float4 v = *reinterpret_cast<const float4*>(
                &hh[(size_t)(kt + br) * NH + colBase + bc4]);
            *reinterpret_cast<float4*>(&Bs[br][bc4]) = v;
        }
        __syncthreads();

#pragma unroll
        for (int k = 0; k < BK; k++) {
            float a[TM], b[TN];
            // vectorized smem loads (32B-aligned)
            float4 a0 = *reinterpret_cast<const float4*>(&As[k][ty * TM]);
            float4 a1 = *reinterpret_cast<const float4*>(&As[k][ty * TM + 4]);
            a[0] = a0.x; a[1] = a0.y; a[2] = a0.z; a[3] = a0.w;
            a[4] = a1.x; a[5] = a1.y; a[6] = a1.z; a[7] = a1.w;
            float4 b0 = *reinterpret_cast<const float4*>(&Bs[k][tx * TN]);
            float4 b1 = *reinterpret_cast<const float4*>(&Bs[k][tx * TN + 4]);
            b[0] = b0.x; b[1] = b0.y; b[2] = b0.z; b[3] = b0.w;
            b[4] = b1.x; b[5] = b1.y; b[6] = b1.z; b[7] = b1.w;
#pragma unroll
            for (int i = 0; i < TM; i++)
#pragma unroll
                for (int j = 0; j < TN; j++)
                    acc[i][j] = fmaf(a[i], b[j], acc[i][j]);
        }
        __syncthreads();
    }

    // Fused epilogue: gather gate, mul, residual add, tanh
#pragma unroll
    for (int i = 0; i < TM; i++) {
        int m = rowBase + ty * TM + i;
        // token is int32; mask defensively into vocab range so a dtype
        // surprise can't produce an illegal access.
        int tok = token[m] & (NV - 1);
        const float* gate_row = ih + (size_t)tok * NH;
        const float* sin_row  = s_in + (size_t)m * NH;
        float* sout_row       = s_out + (size_t)m * NH;
#pragma unroll
        for (int j = 0; j < TN; j++) {
            int n = colBase + tx * TN + j;
            float val = sin_row[n] + acc[i][j] * gate_row[n];
            sout_row[n] = tanhf(val);
        }
    }
}

extern "C" void kernel_launch(void* const* d_in, const int* in_sizes, int n_in,
                              void* d_out, int out_size)
{
    // Identify inputs by element count (all four are distinct) so we don't
    // depend on metadata ordering:
    //   state: NB*NH      = 2,097,152
    //   token: NB         = 1,024
    //   ih:    NL*NV*NH   = 134,217,728
    //   hh:    NL*NH*NH   = 33,554,432
    const float* state = nullptr;
    const int*   token = nullptr;
    const float* ih    = nullptr;
    const float* hh    = nullptr;
    for (int i = 0; i < n_in; i++) {
        long long sz = in_sizes[i];
        if (sz == (long long)NB * NH)           state = (const float*)d_in[i];
        else if (sz == (long long)NB)           token = (const int*)d_in[i];
        else if (sz == (long long)NL * NV * NH) ih    = (const float*)d_in[i];
        else if (sz == (long long)NL * NH * NH) hh    = (const float*)d_in[i];
    }
    float* out = (float*)d_out;  // [NB, NH] f32

    float* buf0 = nullptr;
    float* buf1 = nullptr;
    cudaGetSymbolAddress((void**)&buf0, g_buf0);
    cudaGetSymbolAddress((void**)&buf1, g_buf1);

    dim3 grid(NH / BN, NB / BM);   // (16, 8) = 128 CTAs
    dim3 block(THREADS);

    const float* src = state;
    for (int l = 0; l < NL; l++) {
        float* dst;
        if (l == NL - 1)       dst = out;
        else if ((l & 1) == 0) dst = buf0;
        else                   dst = buf1;

        const float* hh_l = hh + (size_t)l * NH * NH;
        const float* ih_l = ih + (size_t)l * NV * NH;

        rnn_layer_kernel<<<grid, block>>>(src, hh_l, ih_l, token, dst);

        src = dst;
    }
}

// round 4
// speedup vs baseline: 4.8911x; 4.8911x over previous
#include <cuda_runtime.h>
#include <cuda_bf16.h>
#include <cstdint>
#include <math.h>

#define NB 1024
#define NH 2048
#define NV 8192
#define NL 8

// ---------------- device scratch (no allocs allowed) ----------------
__device__ float g_sf32[2][NB * NH];                    // fp32 state ping-pong
__device__ __nv_bfloat16 g_sbf[2][NB * NH];             // bf16 state ping-pong
__device__ __nv_bfloat16 g_hh_bf[(size_t)NL * NH * NH]; // hh as bf16, [l][k][n]

// ---------------- PTX helpers (all base-ISA, no 'a' features) ----------------
__device__ __forceinline__ uint32_t smem_u32(const void* p) {
    uint32_t a;
    asm("{ .reg .u64 t; cvta.to.shared.u64 t, %1; cvt.u32.u64 %0, t; }" : "=r"(a) : "l"(p));
    return a;
}
__device__ __forceinline__ void cp16(uint32_t saddr, const void* gaddr) {
    asm volatile("cp.async.cg.shared.global [%0], [%1], 16;" :: "r"(saddr), "l"(gaddr) : "memory");
}
__device__ __forceinline__ void cp_commit() {
    asm volatile("cp.async.commit_group;" ::: "memory");
}
__device__ __forceinline__ void ldsm_x4(uint32_t& d0, uint32_t& d1, uint32_t& d2, uint32_t& d3,
                                        uint32_t addr) {
    asm volatile("ldmatrix.sync.aligned.m8n8.x4.shared.b16 {%0,%1,%2,%3}, [%4];"
                 : "=r"(d0), "=r"(d1), "=r"(d2), "=r"(d3) : "r"(addr));
}
__device__ __forceinline__ void ldsm_x4_t(uint32_t& d0, uint32_t& d1, uint32_t& d2, uint32_t& d3,
                                          uint32_t addr) {
    asm volatile("ldmatrix.sync.aligned.m8n8.x4.trans.shared.b16 {%0,%1,%2,%3}, [%4];"
                 : "=r"(d0), "=r"(d1), "=r"(d2), "=r"(d3) : "r"(addr));
}
__device__ __forceinline__ void mma16816(float& c0, float& c1, float& c2, float& c3,
                                         uint32_t a0, uint32_t a1, uint32_t a2, uint32_t a3,
                                         uint32_t b0, uint32_t b1) {
    asm volatile(
        "mma.sync.aligned.m16n8k16.row.col.f32.bf16.bf16.f32 "
        "{%0,%1,%2,%3}, {%4,%5,%6,%7}, {%8,%9}, {%0,%1,%2,%3};"
        : "+f"(c0), "+f"(c1), "+f"(c2), "+f"(c3)
        : "r"(a0), "r"(a1), "r"(a2), "r"(a3), "r"(b0), "r"(b1));
}

// ---------------- tiling ----------------
constexpr int BM = 128, BN = 128, BK = 64;
constexpr int NCH = NH / BK;        // 32 K-chunks
constexpr int PA_B = 144;           // A smem row pitch bytes (64 bf16 + 8 pad)
constexpr int PB_B = 272;           // B smem row pitch bytes (128 bf16 + 8 pad)
constexpr int A_BYTES = BM * PA_B;  // 18432
constexpr int B_BYTES = BK * PB_B;  // 17408
constexpr int BUF = A_BYTES + B_BYTES;  // 35840
constexpr int SMEM_TOTAL = 2 * BUF;     // 71680 (>= epi 128*132*4 = 67584)
constexpr int EPI_PITCH = 132;          // fp32 elems

// ---------------- fused layer kernel ----------------
// C = s_bf[BM rows] @ hh_bf[k][n] ; out = tanh(s_f32 + C * ih[token])
__device__ __forceinline__ void load_chunk(
    int tid, uint32_t smem_base,
    const __nv_bfloat16* a_base,   // s_bf + rowBase*NH
    const __nv_bfloat16* b_base,   // hh_bf_l + colBase
    int kt, int buf)
{
    uint32_t sa = smem_base + buf * BUF;
    uint32_t sb = sa + A_BYTES;
#pragma unroll
    for (int g = 0; g < 4; g++) {           // A: 1024 x 16B
        int idx = tid + g * 256;
        int r = idx >> 3, c = idx & 7;
        cp16(sa + r * PA_B + c * 16, a_base + (size_t)r * NH + kt + c * 8);
    }
#pragma unroll
    for (int g = 0; g < 4; g++) {           // B: 1024 x 16B
        int idx = tid + g * 256;
        int r = idx >> 4, c = idx & 15;
        cp16(sb + r * PB_B + c * 16, b_base + (size_t)(kt + r) * NH + c * 8);
    }
    cp_commit();
}

__global__ __launch_bounds__(256, 1)
void rnn_layer_tc(const __nv_bfloat16* __restrict__ s_bf,
                  const float* __restrict__ s_f32,
                  const __nv_bfloat16* __restrict__ hh_l,  // [NH(k)][NH(n)] bf16
                  const float* __restrict__ ih_l,          // [NV][NH] fp32
                  const int* __restrict__ token,
                  float* __restrict__ out_f32,
                  __nv_bfloat16* __restrict__ out_bf)
{
    extern __shared__ __align__(128) char smem[];
    const uint32_t smem_base = smem_u32(smem);
    const int tid  = threadIdx.x;
    const int lane = tid & 31;
    const int wid  = tid >> 5;
    const int wm   = wid >> 2;   // 0..1 (M)
    const int wn   = wid & 3;    // 0..3 (N)

    const int colBase = blockIdx.x * BN;
    const int rowBase = blockIdx.y * BM;

    const __nv_bfloat16* a_base = s_bf + (size_t)rowBase * NH;
    const __nv_bfloat16* b_base = hh_l + colBase;

    float c[4][4][4];
#pragma unroll
    for (int i = 0; i < 4; i++)
#pragma unroll
        for (int j = 0; j < 4; j++)
#pragma unroll
            for (int k = 0; k < 4; k++) c[i][j][k] = 0.0f;

    // ldmatrix lane addressing components
    const int lrow = lane & 15;        // row within 16
    const int lseg = (lane >> 4) * 8;  // 0 or 8 (element offset)

    load_chunk(tid, smem_base, a_base, b_base, 0, 0);
    load_chunk(tid, smem_base, a_base, b_base, BK, 1);

    for (int ch = 0; ch < NCH; ch++) {
        const int buf = ch & 1;
        if (ch < NCH - 1) asm volatile("cp.async.wait_group 1;" ::: "memory");
        else              asm volatile("cp.async.wait_group 0;" ::: "memory");
        __syncthreads();

        const uint32_t sa = smem_base + buf * BUF;
        const uint32_t sb = sa + A_BYTES;

#pragma unroll
        for (int ks = 0; ks < 4; ks++) {   // 4 x k16 per chunk
            uint32_t a[4][4], b[4][2];
#pragma unroll
            for (int mt = 0; mt < 4; mt++) {
                uint32_t addr = sa + (wm * 64 + mt * 16 + lrow) * PA_B
                                   + (ks * 16 + lseg) * 2;
                ldsm_x4(a[mt][0], a[mt][1], a[mt][2], a[mt][3], addr);
            }
#pragma unroll
            for (int np = 0; np < 2; np++) {   // two ldmatrix cover 4 n-tiles
                uint32_t addr = sb + (ks * 16 + lrow) * PB_B
                                   + (wn * 32 + np * 16 + lseg) * 2;
                uint32_t r0, r1, r2, r3;
                ldsm_x4_t(r0, r1, r2, r3, addr);
                b[np * 2 + 0][0] = r0; b[np * 2 + 0][1] = r1;
                b[np * 2 + 1][0] = r2; b[np * 2 + 1][1] = r3;
            }
#pragma unroll
            for (int mt = 0; mt < 4; mt++)
#pragma unroll
                for (int nt = 0; nt < 4; nt++)
                    mma16816(c[mt][nt][0], c[mt][nt][1], c[mt][nt][2], c[mt][nt][3],
                             a[mt][0], a[mt][1], a[mt][2], a[mt][3],
                             b[nt][0], b[nt][1]);
        }
        __syncthreads();
        if (ch + 2 < NCH)
            load_chunk(tid, smem_base, a_base, b_base, (ch + 2) * BK, buf);
    }

    // ---- stage C to SMEM (reuse tile buffers) ----
    float* epi = (float*)smem;   // [128][EPI_PITCH]
#pragma unroll
    for (int mt = 0; mt < 4; mt++) {
#pragma unroll
        for (int nt = 0; nt < 4; nt++) {
            int r0 = wm * 64 + mt * 16 + (lane >> 2);
            int cc = wn * 32 + nt * 8 + (lane & 3) * 2;
            epi[r0 * EPI_PITCH + cc]           = c[mt][nt][0];
            epi[r0 * EPI_PITCH + cc + 1]       = c[mt][nt][1];
            epi[(r0 + 8) * EPI_PITCH + cc]     = c[mt][nt][2];
            epi[(r0 + 8) * EPI_PITCH + cc + 1] = c[mt][nt][3];
        }
    }
    __syncthreads();

    // ---- coalesced gather + mul + add + tanh ----
    const int col  = tid & 127;
    const int half = tid >> 7;
    const float* resid = s_f32 + (size_t)rowBase * NH + colBase;
#pragma unroll 4
    for (int r = 0; r < 64; r++) {
        int row = half * 64 + r;
        int m = rowBase + row;
        int tok = token[m] & (NV - 1);
        float gate = ih_l[(size_t)tok * NH + colBase + col];
        float acc = epi[row * EPI_PITCH + col];
        float v = tanhf(resid[(size_t)row * NH + col] + acc * gate);
        out_f32[(size_t)m * NH + colBase + col] = v;
        out_bf[(size_t)m * NH + colBase + col] = __float2bfloat16(v);
    }
}

// ---------------- pre-pass kernels ----------------
__global__ void conv_f32_bf16(const float* __restrict__ s, __nv_bfloat16* __restrict__ o) {
    size_t i = ((size_t)blockIdx.x * blockDim.x + threadIdx.x) * 4;
    float4 v = *reinterpret_cast<const float4*>(s + i);
    __nv_bfloat162* p = reinterpret_cast<__nv_bfloat162*>(o + i);
    p[0] = __floats2bfloat162_rn(v.x, v.y);
    p[1] = __floats2bfloat162_rn(v.z, v.w);
}

// ---------------- launch ----------------
extern "C" void kernel_launch(void* const* d_in, const int* in_sizes, int n_in,
                              void* d_out, int out_size)
{
    const float* state = nullptr;
    const int*   token = nullptr;
    const float* ih    = nullptr;
    const float* hh    = nullptr;
    for (int i = 0; i < n_in; i++) {
        long long sz = in_sizes[i];
        if (sz == (long long)NB * NH)           state = (const float*)d_in[i];
        else if (sz == (long long)NB)           token = (const int*)d_in[i];
        else if (sz == (long long)NL * NV * NH) ih    = (const float*)d_in[i];
        else if (sz == (long long)NL * NH * NH) hh    = (const float*)d_in[i];
    }
    float* out = (float*)d_out;

    float* sf32[2]; __nv_bfloat16* sbf[2]; __nv_bfloat16* hh_bf;
    cudaGetSymbolAddress((void**)&sf32[0], g_sf32);
    sf32[1] = sf32[0] + NB * NH;
    cudaGetSymbolAddress((void**)&sbf[0], g_sbf);
    sbf[1] = sbf[0] + NB * NH;
    cudaGetSymbolAddress((void**)&hh_bf, g_hh_bf);

    cudaFuncSetAttribute(rnn_layer_tc, cudaFuncAttributeMaxDynamicSharedMemorySize, SMEM_TOTAL);

    // pre-pass: state -> bf16 ; hh -> bf16 (layout unchanged, [l][k][n])
    conv_f32_bf16<<<NB * NH / 4 / 256, 256>>>(state, sbf[0]);
    conv_f32_bf16<<<(int)((size_t)NL * NH * NH / 4 / 256), 256>>>(hh, hh_bf);

    dim3 grid(NH / BN, NB / BM);  // (16, 8) = 128 CTAs
    const float* src_f32 = state;
    for (int l = 0; l < NL; l++) {
        const __nv_bfloat16* a_bf = sbf[l & 1];
        __nv_bfloat16* next_bf = sbf[(l + 1) & 1];
        float* dst_f32 = (l == NL - 1) ? out : sf32[(l + 1) & 1];

        rnn_layer_tc<<<grid, 256, SMEM_TOTAL>>>(
            a_bf, src_f32,
            hh_bf + (size_t)l * NH * NH,
            ih + (size_t)l * NV * NH,
            token, dst_f32, next_bf);

        src_f32 = dst_f32;
    }
}

// round 5
// speedup vs baseline: 4.9682x; 1.0158x over previous
#include <cuda_runtime.h>
#include <cuda_bf16.h>
#include <cstdint>
#include <math.h>

#define NB 1024
#define NH 2048
#define NV 8192
#define NL 8

// ---------------- device scratch (no allocs allowed) ----------------
__device__ float g_sf32[2][NB * NH];                    // fp32 state ping-pong
__device__ __nv_bfloat16 g_sbf[2][NB * NH];             // bf16 state ping-pong
__device__ __nv_bfloat16 g_hh_bf[(size_t)NL * NH * NH]; // hh as bf16, [l][k][n]

// ---------------- PTX helpers (base ISA only; no sm_103a-only features) ----
__device__ __forceinline__ uint32_t smem_u32(const void* p) {
    uint32_t a;
    asm("{ .reg .u64 t; cvta.to.shared.u64 t, %1; cvt.u32.u64 %0, t; }" : "=r"(a) : "l"(p));
    return a;
}
__device__ __forceinline__ void cp16(uint32_t saddr, const void* gaddr) {
    asm volatile("cp.async.cg.shared.global [%0], [%1], 16;" :: "r"(saddr), "l"(gaddr) : "memory");
}
__device__ __forceinline__ void cp_commit() {
    asm volatile("cp.async.commit_group;" ::: "memory");
}
__device__ __forceinline__ void ldsm_x4(uint32_t& d0, uint32_t& d1, uint32_t& d2, uint32_t& d3,
                                        uint32_t addr) {
    asm volatile("ldmatrix.sync.aligned.m8n8.x4.shared.b16 {%0,%1,%2,%3}, [%4];"
                 : "=r"(d0), "=r"(d1), "=r"(d2), "=r"(d3) : "r"(addr));
}
__device__ __forceinline__ void ldsm_x4_t(uint32_t& d0, uint32_t& d1, uint32_t& d2, uint32_t& d3,
                                          uint32_t addr) {
    asm volatile("ldmatrix.sync.aligned.m8n8.x4.trans.shared.b16 {%0,%1,%2,%3}, [%4];"
                 : "=r"(d0), "=r"(d1), "=r"(d2), "=r"(d3) : "r"(addr));
}
__device__ __forceinline__ void mma16816(float& c0, float& c1, float& c2, float& c3,
                                         uint32_t a0, uint32_t a1, uint32_t a2, uint32_t a3,
                                         uint32_t b0, uint32_t b1) {
    asm volatile(
        "mma.sync.aligned.m16n8k16.row.col.f32.bf16.bf16.f32 "
        "{%0,%1,%2,%3}, {%4,%5,%6,%7}, {%8,%9}, {%0,%1,%2,%3};"
        : "+f"(c0), "+f"(c1), "+f"(c2), "+f"(c3)
        : "r"(a0), "r"(a1), "r"(a2), "r"(a3), "r"(b0), "r"(b1));
}

// ---------------- tiling ----------------
constexpr int BM = 128, BN = 128, BK = 64;
constexpr int NCH = NH / BK;        // 32 K-chunks
constexpr int STAGES = 4;
constexpr int PA_B = 144;           // A smem row pitch bytes (64 bf16 + 8 pad)
constexpr int PB_B = 272;           // B smem row pitch bytes (128 bf16 + 8 pad)
constexpr int A_BYTES = BM * PA_B;  // 18432
constexpr int B_BYTES = BK * PB_B;  // 17408
constexpr int BUF = A_BYTES + B_BYTES;     // 35840
constexpr int SMEM_TOTAL = STAGES * BUF;   // 143360 (>= epi 128*132*4 = 67584)
constexpr int EPI_PITCH = 132;             // fp32 elems

// ---------------- fused layer kernel ----------------
__device__ __forceinline__ void load_chunk(
    int tid, uint32_t smem_base,
    const __nv_bfloat16* a_base,   // s_bf + rowBase*NH
    const __nv_bfloat16* b_base,   // hh_bf_l + colBase
    int kt, int stage)
{
    uint32_t sa = smem_base + stage * BUF;
    uint32_t sb = sa + A_BYTES;
#pragma unroll
    for (int g = 0; g < 4; g++) {           // A: 1024 x 16B
        int idx = tid + g * 256;
        int r = idx >> 3, c = idx & 7;
        cp16(sa + r * PA_B + c * 16, a_base + (size_t)r * NH + kt + c * 8);
    }
#pragma unroll
    for (int g = 0; g < 4; g++) {           // B: 1024 x 16B
        int idx = tid + g * 256;
        int r = idx >> 4, c = idx & 15;
        cp16(sb + r * PB_B + c * 16, b_base + (size_t)(kt + r) * NH + c * 8);
    }
    cp_commit();
}

__global__ __launch_bounds__(256, 1)
void rnn_layer_tc(const __nv_bfloat16* __restrict__ s_bf,
                  const float* __restrict__ s_f32,
                  const __nv_bfloat16* __restrict__ hh_l,  // [NH(k)][NH(n)] bf16
                  const float* __restrict__ ih_l,          // [NV][NH] fp32
                  const int* __restrict__ token,
                  float* __restrict__ out_f32,
                  __nv_bfloat16* __restrict__ out_bf)
{
    extern __shared__ __align__(128) char smem[];
    const uint32_t smem_base = smem_u32(smem);
    const int tid  = threadIdx.x;
    const int lane = tid & 31;
    const int wid  = tid >> 5;
    const int wm   = wid >> 2;   // 0..1 (M)
    const int wn   = wid & 3;    // 0..3 (N)

    const int colBase = blockIdx.x * BN;
    const int rowBase = blockIdx.y * BM;

    const __nv_bfloat16* a_base = s_bf + (size_t)rowBase * NH;
    const __nv_bfloat16* b_base = hh_l + colBase;

    float c[4][4][4];
#pragma unroll
    for (int i = 0; i < 4; i++)
#pragma unroll
        for (int j = 0; j < 4; j++)
#pragma unroll
            for (int k = 0; k < 4; k++) c[i][j][k] = 0.0f;

    // ldmatrix lane addressing components
    const int lrow = lane & 15;        // row within 16
    const int lseg = (lane >> 4) * 8;  // 0 or 8 (element offset)

    // prologue: fill STAGES-1 ring slots
#pragma unroll
    for (int s = 0; s < STAGES - 1; s++)
        load_chunk(tid, smem_base, a_base, b_base, s * BK, s);

    // fragment double buffers
    uint32_t af[2][4][4], bf[2][4][2];

#define LOAD_FRAGS(ks, slot)                                                   \
    {                                                                          \
        _Pragma("unroll")                                                      \
        for (int mt = 0; mt < 4; mt++) {                                       \
            uint32_t addr = sa + (wm * 64 + mt * 16 + lrow) * PA_B             \
                               + ((ks) * 16 + lseg) * 2;                       \
            ldsm_x4(af[slot][mt][0], af[slot][mt][1],                          \
                    af[slot][mt][2], af[slot][mt][3], addr);                   \
        }                                                                      \
        _Pragma("unroll")                                                      \
        for (int np = 0; np < 2; np++) {                                       \
            uint32_t addr = sb + ((ks) * 16 + lrow) * PB_B                     \
                               + (wn * 32 + np * 16 + lseg) * 2;               \
            uint32_t r0, r1, r2, r3;                                           \
            ldsm_x4_t(r0, r1, r2, r3, addr);                                   \
            bf[slot][np * 2 + 0][0] = r0; bf[slot][np * 2 + 0][1] = r1;        \
            bf[slot][np * 2 + 1][0] = r2; bf[slot][np * 2 + 1][1] = r3;        \
        }                                                                      \
    }

    for (int ch = 0; ch < NCH; ch++) {
        asm volatile("cp.async.wait_group %0;" :: "n"(STAGES - 2) : "memory");
        __syncthreads();

        // issue next chunk's loads first (overlap GMEM with compute below);
        // ring slot (ch+STAGES-1)%STAGES was last read at chunk ch-1 -> safe.
        {
            int nxt = ch + STAGES - 1;
            if (nxt < NCH)
                load_chunk(tid, smem_base, a_base, b_base, nxt * BK, nxt & (STAGES - 1));
            else
                cp_commit();   // dummy group keeps wait_group accounting uniform
        }

        const uint32_t sa = smem_base + (ch & (STAGES - 1)) * BUF;
        const uint32_t sb = sa + A_BYTES;

        LOAD_FRAGS(0, 0)
#pragma unroll
        for (int ks = 0; ks < 4; ks++) {
            const int cur = ks & 1;
            if (ks < 3) LOAD_FRAGS(ks + 1, cur ^ 1)
#pragma unroll
            for (int mt = 0; mt < 4; mt++)
#pragma unroll
                for (int nt = 0; nt < 4; nt++)
                    mma16816(c[mt][nt][0], c[mt][nt][1], c[mt][nt][2], c[mt][nt][3],
                             af[cur][mt][0], af[cur][mt][1], af[cur][mt][2], af[cur][mt][3],
                             bf[cur][nt][0], bf[cur][nt][1]);
        }
    }
#undef LOAD_FRAGS

    __syncthreads();   // all warps done reading ring; smem now reusable

    // ---- stage C to SMEM ----
    float* epi = (float*)smem;   // [128][EPI_PITCH]
#pragma unroll
    for (int mt = 0; mt < 4; mt++) {
#pragma unroll
        for (int nt = 0; nt < 4; nt++) {
            int r0 = wm * 64 + mt * 16 + (lane >> 2);
            int cc = wn * 32 + nt * 8 + (lane & 3) * 2;
            epi[r0 * EPI_PITCH + cc]           = c[mt][nt][0];
            epi[r0 * EPI_PITCH + cc + 1]       = c[mt][nt][1];
            epi[(r0 + 8) * EPI_PITCH + cc]     = c[mt][nt][2];
            epi[(r0 + 8) * EPI_PITCH + cc + 1] = c[mt][nt][3];
        }
    }
    __syncthreads();

    // ---- coalesced gather + mul + add + tanh ----
    const int col  = tid & 127;
    const int half = tid >> 7;
    const float* resid = s_f32 + (size_t)rowBase * NH + colBase;
#pragma unroll 4
    for (int r = 0; r < 64; r++) {
        int row = half * 64 + r;
        int m = rowBase + row;
        int tok = token[m] & (NV - 1);
        float gate = ih_l[(size_t)tok * NH + colBase + col];
        float acc = epi[row * EPI_PITCH + col];
        float v = tanhf(resid[(size_t)row * NH + col] + acc * gate);
        out_f32[(size_t)m * NH + colBase + col] = v;
        out_bf[(size_t)m * NH + colBase + col] = __float2bfloat16(v);
    }
}

// ---------------- pre-pass kernels ----------------
__global__ void conv_f32_bf16(const float* __restrict__ s, __nv_bfloat16* __restrict__ o) {
    size_t i = ((size_t)blockIdx.x * blockDim.x + threadIdx.x) * 4;
    float4 v = *reinterpret_cast<const float4*>(s + i);
    __nv_bfloat162* p = reinterpret_cast<__nv_bfloat162*>(o + i);
    p[0] = __floats2bfloat162_rn(v.x, v.y);
    p[1] = __floats2bfloat162_rn(v.z, v.w);
}

// ---------------- launch ----------------
extern "C" void kernel_launch(void* const* d_in, const int* in_sizes, int n_in,
                              void* d_out, int out_size)
{
    const float* state = nullptr;
    const int*   token = nullptr;
    const float* ih    = nullptr;
    const float* hh    = nullptr;
    for (int i = 0; i < n_in; i++) {
        long long sz = in_sizes[i];
        if (sz == (long long)NB * NH)           state = (const float*)d_in[i];
        else if (sz == (long long)NB)           token = (const int*)d_in[i];
        else if (sz == (long long)NL * NV * NH) ih    = (const float*)d_in[i];
        else if (sz == (long long)NL * NH * NH) hh    = (const float*)d_in[i];
    }
    float* out = (float*)d_out;

    float* sf32[2]; __nv_bfloat16* sbf[2]; __nv_bfloat16* hh_bf;
    cudaGetSymbolAddress((void**)&sf32[0], g_sf32);
    sf32[1] = sf32[0] + NB * NH;
    cudaGetSymbolAddress((void**)&sbf[0], g_sbf);
    sbf[1] = sbf[0] + NB * NH;
    cudaGetSymbolAddress((void**)&hh_bf, g_hh_bf);

    cudaFuncSetAttribute(rnn_layer_tc, cudaFuncAttributeMaxDynamicSharedMemorySize, SMEM_TOTAL);

    // pre-pass: state -> bf16 ; hh -> bf16 (layout unchanged, [l][k][n])
    conv_f32_bf16<<<NB * NH / 4 / 256, 256>>>(state, sbf[0]);
    conv_f32_bf16<<<(int)((size_t)NL * NH * NH / 4 / 256), 256>>>(hh, hh_bf);

    dim3 grid(NH / BN, NB / BM);  // (16, 8) = 128 CTAs
    const float* src_f32 = state;
    for (int l = 0; l < NL; l++) {
        const __nv_bfloat16* a_bf = sbf[l & 1];
        __nv_bfloat16* next_bf = sbf[(l + 1) & 1];
        float* dst_f32 = (l == NL - 1) ? out : sf32[(l + 1) & 1];

        rnn_layer_tc<<<grid, 256, SMEM_TOTAL>>>(
            a_bf, src_f32,
            hh_bf + (size_t)l * NH * NH,
            ih + (size_t)l * NV * NH,
            token, dst_f32, next_bf);

        src_f32 = dst_f32;
    }
}

// round 6
// speedup vs baseline: 5.4221x; 1.0914x over previous
#include <cuda_runtime.h>
#include <cuda_bf16.h>
#include <cstdint>
#include <math.h>

#define NB 1024
#define NH 2048
#define NV 8192
#define NL 8

// ---------------- device scratch (no allocs allowed) ----------------
__device__ float g_sf32[2][NB * NH];                    // fp32 state ping-pong
__device__ __nv_bfloat16 g_sbf[2][NB * NH];             // bf16 state ping-pong
__device__ __nv_bfloat16 g_hh_bf[(size_t)NL * NH * NH]; // hh as bf16, [l][k][n]

// ---------------- PTX helpers (base ISA only) ----------------
__device__ __forceinline__ uint32_t smem_u32(const void* p) {
    uint32_t a;
    asm("{ .reg .u64 t; cvta.to.shared.u64 t, %1; cvt.u32.u64 %0, t; }" : "=r"(a) : "l"(p));
    return a;
}
__device__ __forceinline__ void cp16(uint32_t saddr, const void* gaddr) {
    asm volatile("cp.async.cg.shared.global [%0], [%1], 16;" :: "r"(saddr), "l"(gaddr) : "memory");
}
__device__ __forceinline__ void cp_commit() {
    asm volatile("cp.async.commit_group;" ::: "memory");
}
__device__ __forceinline__ void ldsm_x4(uint32_t& d0, uint32_t& d1, uint32_t& d2, uint32_t& d3,
                                        uint32_t addr) {
    asm volatile("ldmatrix.sync.aligned.m8n8.x4.shared.b16 {%0,%1,%2,%3}, [%4];"
                 : "=r"(d0), "=r"(d1), "=r"(d2), "=r"(d3) : "r"(addr));
}
__device__ __forceinline__ void ldsm_x4_t(uint32_t& d0, uint32_t& d1, uint32_t& d2, uint32_t& d3,
                                          uint32_t addr) {
    asm volatile("ldmatrix.sync.aligned.m8n8.x4.trans.shared.b16 {%0,%1,%2,%3}, [%4];"
                 : "=r"(d0), "=r"(d1), "=r"(d2), "=r"(d3) : "r"(addr));
}
__device__ __forceinline__ void mma16816(float& c0, float& c1, float& c2, float& c3,
                                         uint32_t a0, uint32_t a1, uint32_t a2, uint32_t a3,
                                         uint32_t b0, uint32_t b1) {
    asm volatile(
        "mma.sync.aligned.m16n8k16.row.col.f32.bf16.bf16.f32 "
        "{%0,%1,%2,%3}, {%4,%5,%6,%7}, {%8,%9}, {%0,%1,%2,%3};"
        : "+f"(c0), "+f"(c1), "+f"(c2), "+f"(c3)
        : "r"(a0), "r"(a1), "r"(a2), "r"(a3), "r"(b0), "r"(b1));
}

// ---------------- tiling ----------------
// CTA tile 128x64, 8 warps in 4(M) x 2(N), warp tile 32x32. 2 CTAs/SM.
constexpr int BM = 128, BN = 64, BK = 64;
constexpr int NCH = NH / BK;        // 32 K-chunks
constexpr int STAGES = 3;
constexpr int PA_B = 144;           // A smem row pitch (64 bf16 + 8 pad)
constexpr int PB_B = 144;           // B smem row pitch (64 bf16 + 8 pad)
constexpr int A_BYTES = BM * PA_B;  // 18432
constexpr int B_BYTES = BK * PB_B;  // 9216
constexpr int BUF = A_BYTES + B_BYTES;     // 27648
constexpr int SMEM_TOTAL = STAGES * BUF;   // 82944 (>= epi 128*68*4 = 34816)
constexpr int EPI_PITCH = 68;              // fp32 elems

// ---------------- fused layer kernel ----------------
__device__ __forceinline__ void load_chunk(
    int tid, uint32_t smem_base,
    const __nv_bfloat16* a_base,   // s_bf + rowBase*NH
    const __nv_bfloat16* b_base,   // hh_bf_l + colBase
    int kt, int stage)
{
    uint32_t sa = smem_base + stage * BUF;
    uint32_t sb = sa + A_BYTES;
#pragma unroll
    for (int g = 0; g < 4; g++) {           // A: 1024 x 16B (128 rows x 8)
        int idx = tid + g * 256;
        int r = idx >> 3, c = idx & 7;
        cp16(sa + r * PA_B + c * 16, a_base + (size_t)r * NH + kt + c * 8);
    }
#pragma unroll
    for (int g = 0; g < 2; g++) {           // B: 512 x 16B (64 rows x 8)
        int idx = tid + g * 256;
        int r = idx >> 3, c = idx & 7;
        cp16(sb + r * PB_B + c * 16, b_base + (size_t)(kt + r) * NH + c * 8);
    }
    cp_commit();
}

__global__ __launch_bounds__(256, 2)
void rnn_layer_tc(const __nv_bfloat16* __restrict__ s_bf,
                  const float* __restrict__ s_f32,
                  const __nv_bfloat16* __restrict__ hh_l,  // [NH(k)][NH(n)] bf16
                  const float* __restrict__ ih_l,          // [NV][NH] fp32
                  const int* __restrict__ token,
                  float* __restrict__ out_f32,
                  __nv_bfloat16* __restrict__ out_bf)
{
    extern __shared__ __align__(128) char smem[];
    const uint32_t smem_base = smem_u32(smem);
    const int tid  = threadIdx.x;
    const int lane = tid & 31;
    const int wid  = tid >> 5;
    const int wm   = wid & 3;    // 0..3 (M, 32 rows each)
    const int wn   = wid >> 2;   // 0..1 (N, 32 cols each)

    const int colBase = blockIdx.x * BN;
    const int rowBase = blockIdx.y * BM;

    const __nv_bfloat16* a_base = s_bf + (size_t)rowBase * NH;
    const __nv_bfloat16* b_base = hh_l + colBase;

    float c[2][4][4];
#pragma unroll
    for (int i = 0; i < 2; i++)
#pragma unroll
        for (int j = 0; j < 4; j++)
#pragma unroll
            for (int k = 0; k < 4; k++) c[i][j][k] = 0.0f;

    const int lrow = lane & 15;        // row within 16
    const int lseg = (lane >> 4) * 8;  // 0 or 8 (element offset)

    // prologue: fill STAGES-1 ring slots
#pragma unroll
    for (int s = 0; s < STAGES - 1; s++)
        load_chunk(tid, smem_base, a_base, b_base, s * BK, s);

    for (int ch = 0; ch < NCH; ch++) {
        asm volatile("cp.async.wait_group %0;" :: "n"(STAGES - 2) : "memory");
        __syncthreads();

        // issue next chunk's loads (slot was last read at chunk ch-1 -> safe)
        {
            int nxt = ch + STAGES - 1;
            int slot = nxt % STAGES;
            if (nxt < NCH)
                load_chunk(tid, smem_base, a_base, b_base, nxt * BK, slot);
            else
                cp_commit();   // dummy group keeps wait_group accounting uniform
        }

        const uint32_t sa = smem_base + (ch % STAGES) * BUF;
        const uint32_t sb = sa + A_BYTES;

#pragma unroll
        for (int ks = 0; ks < 4; ks++) {
            uint32_t af[2][4], bfr[4][2];
#pragma unroll
            for (int mt = 0; mt < 2; mt++) {
                uint32_t addr = sa + (wm * 32 + mt * 16 + lrow) * PA_B
                                   + (ks * 16 + lseg) * 2;
                ldsm_x4(af[mt][0], af[mt][1], af[mt][2], af[mt][3], addr);
            }
#pragma unroll
            for (int np = 0; np < 2; np++) {
                uint32_t addr = sb + (ks * 16 + lrow) * PB_B
                                   + (wn * 32 + np * 16 + lseg) * 2;
                uint32_t r0, r1, r2, r3;
                ldsm_x4_t(r0, r1, r2, r3, addr);
                bfr[np * 2 + 0][0] = r0; bfr[np * 2 + 0][1] = r1;
                bfr[np * 2 + 1][0] = r2; bfr[np * 2 + 1][1] = r3;
            }
#pragma unroll
            for (int mt = 0; mt < 2; mt++)
#pragma unroll
                for (int nt = 0; nt < 4; nt++)
                    mma16816(c[mt][nt][0], c[mt][nt][1], c[mt][nt][2], c[mt][nt][3],
                             af[mt][0], af[mt][1], af[mt][2], af[mt][3],
                             bfr[nt][0], bfr[nt][1]);
        }
    }

    __syncthreads();   // all warps done reading ring; smem now reusable

    // ---- stage C to SMEM ----
    float* epi = (float*)smem;   // [128][EPI_PITCH]
#pragma unroll
    for (int mt = 0; mt < 2; mt++) {
#pragma unroll
        for (int nt = 0; nt < 4; nt++) {
            int r0 = wm * 32 + mt * 16 + (lane >> 2);
            int cc = wn * 32 + nt * 8 + (lane & 3) * 2;
            epi[r0 * EPI_PITCH + cc]           = c[mt][nt][0];
            epi[r0 * EPI_PITCH + cc + 1]       = c[mt][nt][1];
            epi[(r0 + 8) * EPI_PITCH + cc]     = c[mt][nt][2];
            epi[(r0 + 8) * EPI_PITCH + cc + 1] = c[mt][nt][3];
        }
    }
    __syncthreads();

    // ---- coalesced gather + mul + add + tanh ----
    const int col   = tid & 63;
    const int group = tid >> 6;   // 0..3 -> rows group*32 .. +31
    const float* resid = s_f32 + (size_t)rowBase * NH + colBase;
#pragma unroll 4
    for (int r = 0; r < 32; r++) {
        int row = group * 32 + r;
        int m = rowBase + row;
        int tok = token[m] & (NV - 1);
        float gate = ih_l[(size_t)tok * NH + colBase + col];
        float acc = epi[row * EPI_PITCH + col];
        float v = tanhf(resid[(size_t)row * NH + col] + acc * gate);
        out_f32[(size_t)m * NH + colBase + col] = v;
        out_bf[(size_t)m * NH + colBase + col] = __float2bfloat16(v);
    }
}

// ---------------- pre-pass kernels ----------------
__global__ void conv_f32_bf16(const float* __restrict__ s, __nv_bfloat16* __restrict__ o) {
    size_t i = ((size_t)blockIdx.x * blockDim.x + threadIdx.x) * 4;
    float4 v = *reinterpret_cast<const float4*>(s + i);
    __nv_bfloat162* p = reinterpret_cast<__nv_bfloat162*>(o + i);
    p[0] = __floats2bfloat162_rn(v.x, v.y);
    p[1] = __floats2bfloat162_rn(v.z, v.w);
}

// ---------------- launch ----------------
extern "C" void kernel_launch(void* const* d_in, const int* in_sizes, int n_in,
                              void* d_out, int out_size)
{
    const float* state = nullptr;
    const int*   token = nullptr;
    const float* ih    = nullptr;
    const float* hh    = nullptr;
    for (int i = 0; i < n_in; i++) {
        long long sz = in_sizes[i];
        if (sz == (long long)NB * NH)           state = (const float*)d_in[i];
        else if (sz == (long long)NB)           token = (const int*)d_in[i];
        else if (sz == (long long)NL * NV * NH) ih    = (const float*)d_in[i];
        else if (sz == (long long)NL * NH * NH) hh    = (const float*)d_in[i];
    }
    float* out = (float*)d_out;

    float* sf32[2]; __nv_bfloat16* sbf[2]; __nv_bfloat16* hh_bf;
    cudaGetSymbolAddress((void**)&sf32[0], g_sf32);
    sf32[1] = sf32[0] + NB * NH;
    cudaGetSymbolAddress((void**)&sbf[0], g_sbf);
    sbf[1] = sbf[0] + NB * NH;
    cudaGetSymbolAddress((void**)&hh_bf, g_hh_bf);

    cudaFuncSetAttribute(rnn_layer_tc, cudaFuncAttributeMaxDynamicSharedMemorySize, SMEM_TOTAL);

    // pre-pass: state -> bf16 ; hh -> bf16 (layout unchanged, [l][k][n])
    conv_f32_bf16<<<NB * NH / 4 / 256, 256>>>(state, sbf[0]);
    conv_f32_bf16<<<(int)((size_t)NL * NH * NH / 4 / 256), 256>>>(hh, hh_bf);

    dim3 grid(NH / BN, NB / BM);  // (32, 8) = 256 CTAs, 2 per SM
    const float* src_f32 = state;
    for (int l = 0; l < NL; l++) {
        const __nv_bfloat16* a_bf = sbf[l & 1];
        __nv_bfloat16* next_bf = sbf[(l + 1) & 1];
        float* dst_f32 = (l == NL - 1) ? out : sf32[(l + 1) & 1];

        rnn_layer_tc<<<grid, 256, SMEM_TOTAL>>>(
            a_bf, src_f32,
            hh_bf + (size_t)l * NH * NH,
            ih + (size_t)l * NV * NH,
            token, dst_f32, next_bf);

        src_f32 = dst_f32;
    }
}

// round 7
// speedup vs baseline: 6.2195x; 1.1470x over previous
#include <cuda_runtime.h>
#include <cuda_bf16.h>
#include <cstdint>
#include <math.h>

#define NB 1024
#define NH 2048
#define NV 8192
#define NL 8

// ---------------- device scratch (no allocs allowed) ----------------
__device__ float g_sf32[2][NB * NH];                    // fp32 state ping-pong
__device__ __nv_bfloat16 g_sbf[2][NB * NH];             // bf16 state ping-pong
__device__ __nv_bfloat16 g_hh_bf[(size_t)NL * NH * NH]; // hh as bf16, [l][k][n]

// ---------------- PTX helpers (base ISA only; compiles at compute_103) ------
__device__ __forceinline__ uint32_t smem_u32(const void* p) {
    uint32_t a;
    asm("{ .reg .u64 t; cvta.to.shared.u64 t, %1; cvt.u32.u64 %0, t; }" : "=r"(a) : "l"(p));
    return a;
}
__device__ __forceinline__ void cp16(uint32_t saddr, const void* gaddr) {
    asm volatile("cp.async.cg.shared.global [%0], [%1], 16;" :: "r"(saddr), "l"(gaddr) : "memory");
}
__device__ __forceinline__ void cp_commit() {
    asm volatile("cp.async.commit_group;" ::: "memory");
}
__device__ __forceinline__ void mbar_init(uint32_t mbar, uint32_t cnt) {
    asm volatile("mbarrier.init.shared.b64 [%0], %1;" :: "r"(mbar), "r"(cnt) : "memory");
}
__device__ __forceinline__ void mbar_arrive(uint32_t mbar) {
    asm volatile("mbarrier.arrive.shared.b64 _, [%0];" :: "r"(mbar) : "memory");
}
__device__ __forceinline__ void mbar_wait(uint32_t mbar, uint32_t parity) {
    uint32_t done;
    asm volatile("{ .reg .pred p; mbarrier.try_wait.parity.shared.b64 p, [%1], %2; selp.b32 %0,1,0,p; }"
                 : "=r"(done) : "r"(mbar), "r"(parity) : "memory");
    while (!done) {
        asm volatile("{ .reg .pred p; mbarrier.try_wait.parity.shared.b64 p, [%1], %2; selp.b32 %0,1,0,p; }"
                     : "=r"(done) : "r"(mbar), "r"(parity) : "memory");
    }
}
__device__ __forceinline__ void ldsm_x4(uint32_t& d0, uint32_t& d1, uint32_t& d2, uint32_t& d3,
                                        uint32_t addr) {
    asm volatile("ldmatrix.sync.aligned.m8n8.x4.shared.b16 {%0,%1,%2,%3}, [%4];"
                 : "=r"(d0), "=r"(d1), "=r"(d2), "=r"(d3) : "r"(addr));
}
__device__ __forceinline__ void ldsm_x4_t(uint32_t& d0, uint32_t& d1, uint32_t& d2, uint32_t& d3,
                                          uint32_t addr) {
    asm volatile("ldmatrix.sync.aligned.m8n8.x4.trans.shared.b16 {%0,%1,%2,%3}, [%4];"
                 : "=r"(d0), "=r"(d1), "=r"(d2), "=r"(d3) : "r"(addr));
}
__device__ __forceinline__ void mma16816(float& c0, float& c1, float& c2, float& c3,
                                         uint32_t a0, uint32_t a1, uint32_t a2, uint32_t a3,
                                         uint32_t b0, uint32_t b1) {
    asm volatile(
        "mma.sync.aligned.m16n8k16.row.col.f32.bf16.bf16.f32 "
        "{%0,%1,%2,%3}, {%4,%5,%6,%7}, {%8,%9}, {%0,%1,%2,%3};"
        : "+f"(c0), "+f"(c1), "+f"(c2), "+f"(c3)
        : "r"(a0), "r"(a1), "r"(a2), "r"(a3), "r"(b0), "r"(b1));
}

// ---------------- tiling ----------------
// CTA tile 128x64. 8 consumer warps (4M x 2N, warp tile 32x32) + 1 producer warp.
constexpr int BM = 128, BN = 64, BK = 64;
constexpr int NCH = NH / BK;        // 32 K-chunks
constexpr int STAGES = 4;
constexpr int PA_B = 144;           // A smem row pitch (64 bf16 + 8 pad)
constexpr int PB_B = 144;           // B smem row pitch
constexpr int A_BYTES = BM * PA_B;  // 18432
constexpr int B_BYTES = BK * PB_B;  // 9216
constexpr int BUF = A_BYTES + B_BYTES;       // 27648
constexpr int MBAR_OFF = STAGES * BUF;       // 110592
constexpr int SMEM_TOTAL = MBAR_OFF + STAGES * 16;  // 110656
constexpr int EPI_PITCH = 68;                // fp32 elems (epi reuses stage mem)

__global__ __launch_bounds__(288, 2)
void rnn_layer_tc(const __nv_bfloat16* __restrict__ s_bf,
                  const float* __restrict__ s_f32,
                  const __nv_bfloat16* __restrict__ hh_l,  // [NH(k)][NH(n)] bf16
                  const float* __restrict__ ih_l,          // [NV][NH] fp32
                  const int* __restrict__ token,
                  float* __restrict__ out_f32,
                  __nv_bfloat16* __restrict__ out_bf)
{
    extern __shared__ __align__(128) char smem[];
    const uint32_t smem_base = smem_u32(smem);
    const uint32_t mbar_base = smem_base + MBAR_OFF;
    const int tid  = threadIdx.x;
    const int lane = tid & 31;
    const int wid  = tid >> 5;       // 0..7 consumers, 8 producer

    const int colBase = blockIdx.x * BN;
    const int rowBase = blockIdx.y * BM;

    const __nv_bfloat16* a_base = s_bf + (size_t)rowBase * NH;
    const __nv_bfloat16* b_base = hh_l + colBase;

    if (tid == 0) {
#pragma unroll
        for (int s = 0; s < STAGES; s++) {
            mbar_init(mbar_base + s * 16, 32);      // full[s]: producer threads
            mbar_init(mbar_base + s * 16 + 8, 8);   // empty[s]: consumer warps
        }
    }
    __syncthreads();

    float c[2][4][4];
#pragma unroll
    for (int i = 0; i < 2; i++)
#pragma unroll
        for (int j = 0; j < 4; j++)
#pragma unroll
            for (int k = 0; k < 4; k++) c[i][j][k] = 0.0f;

    if (wid == 8) {
        // ================= producer warp =================
        int phase = 1;   // fresh-barrier wait on parity 1 passes immediately
        for (int ch = 0; ch < NCH; ch++) {
            const int s = ch & (STAGES - 1);
            mbar_wait(mbar_base + s * 16 + 8, phase);   // empty[s]
            const uint32_t sa = smem_base + s * BUF;
            const uint32_t sb = sa + A_BYTES;
            const int kt = ch * BK;
#pragma unroll
            for (int i = 0; i < 32; i++) {   // A: 1024 x 16B
                int idx = i * 32 + lane;
                int r = idx >> 3, cc = idx & 7;
                cp16(sa + r * PA_B + cc * 16, a_base + (size_t)r * NH + kt + cc * 8);
            }
#pragma unroll
            for (int i = 0; i < 16; i++) {   // B: 512 x 16B
                int idx = i * 32 + lane;
                int r = idx >> 3, cc = idx & 7;
                cp16(sb + r * PB_B + cc * 16, b_base + (size_t)(kt + r) * NH + cc * 8);
            }
            cp_commit();
            if (ch >= 2) {
                asm volatile("cp.async.wait_group 2;" ::: "memory");
                mbar_arrive(mbar_base + ((ch - 2) & (STAGES - 1)) * 16);  // full
            }
            if (s == STAGES - 1) phase ^= 1;
        }
        asm volatile("cp.async.wait_group 1;" ::: "memory");
        mbar_arrive(mbar_base + ((NCH - 2) & (STAGES - 1)) * 16);
        asm volatile("cp.async.wait_group 0;" ::: "memory");
        mbar_arrive(mbar_base + ((NCH - 1) & (STAGES - 1)) * 16);
    } else {
        // ================= consumer warps =================
        const int wm = wid & 3;    // 0..3 (M, 32 rows)
        const int wn = wid >> 2;   // 0..1 (N, 32 cols)
        const int lrow = lane & 15;
        const int lseg = (lane >> 4) * 8;
        int phase = 0;
        for (int ch = 0; ch < NCH; ch++) {
            const int s = ch & (STAGES - 1);
            mbar_wait(mbar_base + s * 16, phase);       // full[s]
            const uint32_t sa = smem_base + s * BUF;
            const uint32_t sb = sa + A_BYTES;
#pragma unroll
            for (int ks = 0; ks < 4; ks++) {
                uint32_t af[2][4], bfr[4][2];
#pragma unroll
                for (int mt = 0; mt < 2; mt++) {
                    uint32_t addr = sa + (wm * 32 + mt * 16 + lrow) * PA_B
                                       + (ks * 16 + lseg) * 2;
                    ldsm_x4(af[mt][0], af[mt][1], af[mt][2], af[mt][3], addr);
                }
#pragma unroll
                for (int np = 0; np < 2; np++) {
                    uint32_t addr = sb + (ks * 16 + lrow) * PB_B
                                       + (wn * 32 + np * 16 + lseg) * 2;
                    uint32_t r0, r1, r2, r3;
                    ldsm_x4_t(r0, r1, r2, r3, addr);
                    bfr[np * 2 + 0][0] = r0; bfr[np * 2 + 0][1] = r1;
                    bfr[np * 2 + 1][0] = r2; bfr[np * 2 + 1][1] = r3;
                }
#pragma unroll
                for (int mt = 0; mt < 2; mt++)
#pragma unroll
                    for (int nt = 0; nt < 4; nt++)
                        mma16816(c[mt][nt][0], c[mt][nt][1], c[mt][nt][2], c[mt][nt][3],
                                 af[mt][0], af[mt][1], af[mt][2], af[mt][3],
                                 bfr[nt][0], bfr[nt][1]);
            }
            __syncwarp();
            if (lane == 0) mbar_arrive(mbar_base + s * 16 + 8);  // empty[s]
            if (s == STAGES - 1) phase ^= 1;
        }
    }

    __syncthreads();   // producer drained, consumers done; smem reusable

    // ---- stage C to SMEM (consumer warps) ----
    float* epi = (float*)smem;   // [128][EPI_PITCH]
    if (wid < 8) {
        const int wm = wid & 3;
        const int wn = wid >> 2;
#pragma unroll
        for (int mt = 0; mt < 2; mt++) {
#pragma unroll
            for (int nt = 0; nt < 4; nt++) {
                int r0 = wm * 32 + mt * 16 + (lane >> 2);
                int cc = wn * 32 + nt * 8 + (lane & 3) * 2;
                epi[r0 * EPI_PITCH + cc]           = c[mt][nt][0];
                epi[r0 * EPI_PITCH + cc + 1]       = c[mt][nt][1];
                epi[(r0 + 8) * EPI_PITCH + cc]     = c[mt][nt][2];
                epi[(r0 + 8) * EPI_PITCH + cc + 1] = c[mt][nt][3];
            }
        }
    }
    __syncthreads();

    // ---- coalesced gather + mul + add + tanh ----
    if (tid < 256) {
        const int col   = tid & 63;
        const int group = tid >> 6;   // 0..3 -> rows group*32 .. +31
        const float* resid = s_f32 + (size_t)rowBase * NH + colBase;
#pragma unroll 4
        for (int r = 0; r < 32; r++) {
            int row = group * 32 + r;
            int m = rowBase + row;
            int tok = token[m] & (NV - 1);
            float gate = ih_l[(size_t)tok * NH + colBase + col];
            float acc = epi[row * EPI_PITCH + col];
            float v = tanhf(resid[(size_t)row * NH + col] + acc * gate);
            out_f32[(size_t)m * NH + colBase + col] = v;
            out_bf[(size_t)m * NH + colBase + col] = __float2bfloat16(v);
        }
    }
}

// ---------------- pre-pass kernels ----------------
__global__ void conv_f32_bf16(const float* __restrict__ s, __nv_bfloat16* __restrict__ o) {
    size_t i = ((size_t)blockIdx.x * blockDim.x + threadIdx.x) * 4;
    float4 v = *reinterpret_cast<const float4*>(s + i);
    __nv_bfloat162* p = reinterpret_cast<__nv_bfloat162*>(o + i);
    p[0] = __floats2bfloat162_rn(v.x, v.y);
    p[1] = __floats2bfloat162_rn(v.z, v.w);
}

// ---------------- launch ----------------
extern "C" void kernel_launch(void* const* d_in, const int* in_sizes, int n_in,
                              void* d_out, int out_size)
{
    const float* state = nullptr;
    const int*   token = nullptr;
    const float* ih    = nullptr;
    const float* hh    = nullptr;
    for (int i = 0; i < n_in; i++) {
        long long sz = in_sizes[i];
        if (sz == (long long)NB * NH)           state = (const float*)d_in[i];
        else if (sz == (long long)NB)           token = (const int*)d_in[i];
        else if (sz == (long long)NL * NV * NH) ih    = (const float*)d_in[i];
        else if (sz == (long long)NL * NH * NH) hh    = (const float*)d_in[i];
    }
    float* out = (float*)d_out;

    float* sf32[2]; __nv_bfloat16* sbf[2]; __nv_bfloat16* hh_bf;
    cudaGetSymbolAddress((void**)&sf32[0], g_sf32);
    sf32[1] = sf32[0] + NB * NH;
    cudaGetSymbolAddress((void**)&sbf[0], g_sbf);
    sbf[1] = sbf[0] + NB * NH;
    cudaGetSymbolAddress((void**)&hh_bf, g_hh_bf);

    cudaFuncSetAttribute(rnn_layer_tc, cudaFuncAttributeMaxDynamicSharedMemorySize, SMEM_TOTAL);

    // pre-pass: state -> bf16 ; hh -> bf16 (layout unchanged, [l][k][n])
    conv_f32_bf16<<<NB * NH / 4 / 256, 256>>>(state, sbf[0]);
    conv_f32_bf16<<<(int)((size_t)NL * NH * NH / 4 / 256), 256>>>(hh, hh_bf);

    dim3 grid(NH / BN, NB / BM);  // (32, 8) = 256 CTAs, 2 per SM
    const float* src_f32 = state;
    for (int l = 0; l < NL; l++) {
        const __nv_bfloat16* a_bf = sbf[l & 1];
        __nv_bfloat16* next_bf = sbf[(l + 1) & 1];
        float* dst_f32 = (l == NL - 1) ? out : sf32[(l + 1) & 1];

        rnn_layer_tc<<<grid, 288, SMEM_TOTAL>>>(
            a_bf, src_f32,
            hh_bf + (size_t)l * NH * NH,
            ih + (size_t)l * NV * NH,
            token, dst_f32, next_bf);

        src_f32 = dst_f32;
    }
}